// round 2
// baseline (speedup 1.0000x reference)
#include <cuda_runtime.h>

// ---------------------------------------------------------------------------
// QuantumDMRGLayer: MPS chain contraction.
//   left[b]  = (x[b,0]@A_left)  · prod_{s=0..pos-1} M_s        (v @ M)
//   right[b] = prod_{s=pos..nmat-1} M_s · (x[b,L-1]@A_right)   (M @ v, from right)
//   out[b,l] = sum_{m,n} left[m] T[m,n,l] right[n]
// with M_s = x[b,s+1,0]*A_mid[s,0] + x[b,s+1,1]*A_mid[s,1]
//
// Strategy: lane-per-output-index (16 lanes per chain), 2 samples per lane
// group to amortize A loads, f32x2 packed FMAs (FFMA2), A repacked chunk-major
// in global scratch (L1-resident), v exchanged via warp-private shared memory
// with ping-pong buffers and __syncwarp only (no CTA barriers in main loop).
// ---------------------------------------------------------------------------

#define MDIM 16

// Repacked A: [dir][site][chunk 0..7][lane 0..15] float4
//   dir 0 (left, v@M):  chunk c<4 -> (A0[4c+k][lane])_k ; c>=4 -> A1 columns
//   dir 1 (right, M@v): chunk c<4 -> (A0[lane][4c+k])_k ; c>=4 -> A1 rows
__device__ float4 g_AT[2 * 200 * 8 * MDIM];          // up to L=202, 800KB
__device__ float  g_vout[2][4096 * MDIM];            // final left/right vectors

// ---------------------------- f32x2 helpers --------------------------------
__device__ __forceinline__ unsigned long long mul2(unsigned long long a, unsigned long long b) {
    unsigned long long d;
    asm("mul.rn.f32x2 %0, %1, %2;" : "=l"(d) : "l"(a), "l"(b));
    return d;
}
__device__ __forceinline__ unsigned long long fma2(unsigned long long a, unsigned long long b, unsigned long long c) {
    unsigned long long d;
    asm("fma.rn.f32x2 %0, %1, %2, %3;" : "=l"(d) : "l"(a), "l"(b), "l"(c));
    return d;
}
__device__ __forceinline__ unsigned long long add2(unsigned long long a, unsigned long long b) {
    unsigned long long d;
    asm("add.rn.f32x2 %0, %1, %2;" : "=l"(d) : "l"(a), "l"(b));
    return d;
}
__device__ __forceinline__ float hsum2(unsigned long long v) {
    float lo, hi;
    asm("mov.b64 {%0, %1}, %2;" : "=f"(lo), "=f"(hi) : "l"(v));
    return lo + hi;
}

// ---------------------------- prep: repack A -------------------------------
__global__ void prep_kernel(const float* __restrict__ A_mid, int nsites) {
    int idx = blockIdx.x * blockDim.x + threadIdx.x;
    int total = 2 * nsites * 8 * MDIM;
    if (idx >= total) return;
    int lane = idx & 15;
    int c    = (idx >> 4) & 7;
    int sc   = idx >> 7;
    int s    = sc % nsites;
    int dir  = sc / nsites;
    int d    = c >> 2;            // 0 -> A0, 1 -> A1
    int c4   = (c & 3) * 4;
    const float* base = A_mid + ((size_t)(s * 2 + d)) * MDIM * MDIM;
    float4 v;
    if (dir == 0) {               // transposed columns (for v @ M)
        v.x = base[(c4 + 0) * MDIM + lane];
        v.y = base[(c4 + 1) * MDIM + lane];
        v.z = base[(c4 + 2) * MDIM + lane];
        v.w = base[(c4 + 3) * MDIM + lane];
    } else {                      // natural rows (for M @ v)
        v = *reinterpret_cast<const float4*>(base + lane * MDIM + c4);
    }
    g_AT[((size_t)(dir * nsites + s) * 8 + c) * MDIM + lane] = v;
}

// ------------------------- one chain micro-step ----------------------------
// v_new[lane] = x0 * <v, A0col/row(lane)> + x1 * <v, A1col/row(lane)>
__device__ __forceinline__ float mps_compute(const ulonglong2* __restrict__ Ar,
                                             const ulonglong2* __restrict__ vv,
                                             float2 xx) {
    ulonglong2 q0 = vv[0], q1 = vv[1], q2 = vv[2], q3 = vv[3];
    unsigned long long a0a = mul2(q0.x, Ar[0].x);
    unsigned long long a0b = mul2(q0.y, Ar[0].y);
    unsigned long long a1a = mul2(q0.x, Ar[4].x);
    unsigned long long a1b = mul2(q0.y, Ar[4].y);
    a0a = fma2(q1.x, Ar[1].x, a0a);  a0b = fma2(q1.y, Ar[1].y, a0b);
    a1a = fma2(q1.x, Ar[5].x, a1a);  a1b = fma2(q1.y, Ar[5].y, a1b);
    a0a = fma2(q2.x, Ar[2].x, a0a);  a0b = fma2(q2.y, Ar[2].y, a0b);
    a1a = fma2(q2.x, Ar[6].x, a1a);  a1b = fma2(q2.y, Ar[6].y, a1b);
    a0a = fma2(q3.x, Ar[3].x, a0a);  a0b = fma2(q3.y, Ar[3].y, a0b);
    a1a = fma2(q3.x, Ar[7].x, a1a);  a1b = fma2(q3.y, Ar[7].y, a1b);
    float s0 = hsum2(add2(a0a, a0b));
    float s1 = hsum2(add2(a1a, a1b));
    return fmaf(xx.y, s1, xx.x * s0);
}

// ----------------------------- main chain kernel ---------------------------
// grid: (ceil(B/16), 2)  block: 128 threads = 4 warps = 8 groups of 16 lanes,
// each group advances 2 samples' chains (same direction).
__global__ void __launch_bounds__(128, 2)
chain_kernel(const float* __restrict__ inputs,
             const float* __restrict__ A_left,
             const float* __restrict__ A_right,
             const int* __restrict__ pos_ptr,
             int B, int L) {
    const int nmat = L - 2;
    const int dir = blockIdx.y;
    const int b0  = blockIdx.x * 16;
    const int XL  = 2 * L;

    __shared__ float sh_x[16 * 400];                    // per-sample input rows
    __shared__ __align__(16) float sh_v[2][16][MDIM];   // ping-pong chain vectors

    int tid = threadIdx.x;
    // bulk-copy the 16 samples' input rows (contiguous) into shared
    {
        int avail = B - b0; if (avail > 16) avail = 16;
        const float4* src4 = reinterpret_cast<const float4*>(inputs + (size_t)b0 * XL);
        float4* dst4 = reinterpret_cast<float4*>(sh_x);
        int n4 = avail * (XL / 4);
        for (int i = tid; i < n4; i += blockDim.x) dst4[i] = src4[i];
    }
    __syncthreads();

    const int lane       = tid & 15;
    const int group      = tid >> 4;        // 0..7
    const int sampleBase = group * 2;

    int pos = pos_ptr ? *pos_ptr : 98;
    if (pos < 0) pos = 0;
    if (pos > nmat) pos = nmat;
    const int nsteps = (dir == 0) ? pos : (nmat - pos);

    // init boundary vectors
    {
        const float* Ab = (dir == 0) ? A_left : A_right;
        const int xsite = (dir == 0) ? 0 : (L - 1);
        float e0 = Ab[lane], e1 = Ab[MDIM + lane];
        #pragma unroll
        for (int k = 0; k < 2; k++) {
            int sIdx = sampleBase + k;
            float x0 = sh_x[sIdx * XL + xsite * 2];
            float x1 = sh_x[sIdx * XL + xsite * 2 + 1];
            sh_v[0][sIdx][lane] = fmaf(x1, e1, x0 * e0);
        }
    }
    __syncwarp();

    int buf = 0;
    const ulonglong2* Abase =
        reinterpret_cast<const ulonglong2*>(g_AT) + (size_t)dir * nmat * 8 * MDIM + lane;
    // address of (mat m, chunk c): Abase[(m*8 + c) * 16]

    ulonglong2 Ar[8], Br[8];
    if (nsteps > 0) {
        int m0 = dir ? (nmat - 1) : 0;
        #pragma unroll
        for (int c = 0; c < 8; c++) Ar[c] = Abase[(m0 * 8 + c) * MDIM];
    }

    int i = 0;
    while (i < nsteps) {
        if (i + 1 < nsteps) {
            int mn = dir ? (nmat - 2 - i) : (i + 1);
            #pragma unroll
            for (int c = 0; c < 8; c++) Br[c] = Abase[(mn * 8 + c) * MDIM];
        }
        {
            int mi = dir ? (nmat - 1 - i) : i;
            int site = mi + 1;
            #pragma unroll
            for (int k = 0; k < 2; k++) {
                int sIdx = sampleBase + k;
                const ulonglong2* vv = reinterpret_cast<const ulonglong2*>(sh_v[buf][sIdx]);
                float2 xx = *reinterpret_cast<const float2*>(&sh_x[sIdx * XL + site * 2]);
                sh_v[buf ^ 1][sIdx][lane] = mps_compute(Ar, vv, xx);
            }
            __syncwarp();
            buf ^= 1; i++;
        }
        if (i >= nsteps) break;
        if (i + 1 < nsteps) {
            int mn = dir ? (nmat - 2 - i) : (i + 1);
            #pragma unroll
            for (int c = 0; c < 8; c++) Ar[c] = Abase[(mn * 8 + c) * MDIM];
        }
        {
            int mi = dir ? (nmat - 1 - i) : i;
            int site = mi + 1;
            #pragma unroll
            for (int k = 0; k < 2; k++) {
                int sIdx = sampleBase + k;
                const ulonglong2* vv = reinterpret_cast<const ulonglong2*>(sh_v[buf][sIdx]);
                float2 xx = *reinterpret_cast<const float2*>(&sh_x[sIdx * XL + site * 2]);
                sh_v[buf ^ 1][sIdx][lane] = mps_compute(Br, vv, xx);
            }
            __syncwarp();
            buf ^= 1; i++;
        }
    }

    #pragma unroll
    for (int k = 0; k < 2; k++) {
        int b = b0 + sampleBase + k;
        if (b < B) g_vout[dir][b * MDIM + lane] = sh_v[buf][sampleBase + k][lane];
    }
}

// ----------------------------- final contraction ---------------------------
// out[b,l] = sum_m left[b,m] * sum_n T[m,n,l] * right[b,n]
__global__ void finish_kernel(const float* __restrict__ T_out,
                              float* __restrict__ out, int B, int NBL) {
    __shared__ float sh_T[MDIM * MDIM * 16];  // up to NBL=16
    __shared__ float sh_l[16][MDIM + 1], sh_r[16][MDIM + 1];
    int b0 = blockIdx.x * 16;
    int tid = threadIdx.x, nt = blockDim.x;
    for (int i = tid; i < MDIM * MDIM * NBL; i += nt) sh_T[i] = T_out[i];
    for (int i = tid; i < 16 * MDIM; i += nt) {
        int s = i >> 4, m = i & 15;
        int b = b0 + s;
        float lv = 0.f, rv = 0.f;
        if (b < B) { lv = g_vout[0][b * MDIM + m]; rv = g_vout[1][b * MDIM + m]; }
        sh_l[s][m] = lv; sh_r[s][m] = rv;
    }
    __syncthreads();
    if (tid < 16 * NBL) {
        int s = tid / NBL, l = tid % NBL;
        int b = b0 + s;
        float acc = 0.f;
        #pragma unroll
        for (int m = 0; m < MDIM; m++) {
            float part = 0.f;
            #pragma unroll
            for (int n = 0; n < MDIM; n++)
                part = fmaf(sh_r[s][n], sh_T[(m * MDIM + n) * NBL + l], part);
            acc = fmaf(sh_l[s][m], part, acc);
        }
        if (b < B) out[b * NBL + l] = acc;
    }
}

// ------------------------------- launch ------------------------------------
extern "C" void kernel_launch(void* const* d_in, const int* in_sizes, int n_in,
                              void* d_out, int out_size) {
    const float* inputs  = (const float*)d_in[0];
    const float* A_left  = (const float*)d_in[1];
    const float* A_mid   = (const float*)d_in[2];
    const float* A_right = (const float*)d_in[3];
    const float* T_out   = (const float*)d_in[4];
    const int*   pos_ptr = (n_in >= 6) ? (const int*)d_in[5] : nullptr;

    int M    = in_sizes[1] / 2;                 // expect 16
    int nmat = in_sizes[2] / (2 * M * M);       // L - 2
    int L    = nmat + 2;
    int B    = in_sizes[0] / (2 * L);
    int NBL  = in_sizes[4] / (M * M);
    (void)out_size;

    int prepTot = 2 * nmat * 8 * MDIM;
    prep_kernel<<<(prepTot + 255) / 256, 256>>>(A_mid, nmat);

    dim3 grid((B + 15) / 16, 2);
    chain_kernel<<<grid, 128>>>(inputs, A_left, A_right, pos_ptr, B, L);

    finish_kernel<<<(B + 15) / 16, 256>>>(T_out, (float*)d_out, B, NBL);
}